// round 15
// baseline (speedup 1.0000x reference)
#include <cuda_runtime.h>
#include <cstdint>

#define S_SEG 8
#define U_CH 128
#define SU 1024                 // S_SEG * U_CH
#define P_MAX 64
#define GROUPS 4                // z-streams per block (128 threads each)
#define NTHREADS 512
#define TILE_FLOATS (3 * S_SEG * U_CH)   // 3072 floats = 12 KB
#define TILE_BYTES (TILE_FLOATS * 4)     // 12288
#define GRID_BLOCKS 296         // 2 per SM

__device__ __forceinline__ unsigned smem_u32(const void* p) {
    unsigned a;
    asm("{ .reg .u64 t; cvta.to.shared.u64 t, %1; cvt.u32.u64 %0, t; }"
        : "=r"(a) : "l"(p));
    return a;
}

// Predicated LDS.128: load only when bit0 of moff is clear (offset is clean then).
__device__ __forceinline__ void lds128_cond(unsigned long long& v0, unsigned long long& v1,
                                            unsigned sbase, unsigned moff) {
    asm volatile(
        "{\n\t"
        ".reg .pred p;\n\t"
        ".reg .u32 f, a;\n\t"
        "and.b32 f, %3, 1;\n\t"
        "setp.eq.u32 p, f, 0;\n\t"
        "add.u32 a, %2, %3;\n\t"
        "@p ld.shared.v2.u64 {%0, %1}, [a];\n\t"
        "}"
        : "+l"(v0), "+l"(v1) : "r"(sbase), "r"(moff));
}

__device__ __forceinline__ void ldsv4(uint4& m, unsigned addr) {
    asm volatile("ld.shared.v4.u32 {%0,%1,%2,%3}, [%4];"
                 : "=r"(m.x), "=r"(m.y), "=r"(m.z), "=r"(m.w) : "r"(addr));
}

__device__ __forceinline__ unsigned long long mul2(unsigned long long a, unsigned long long b) {
    unsigned long long r;
    asm("mul.rn.f32x2 %0, %1, %2;" : "=l"(r) : "l"(a), "l"(b));
    return r;
}

__device__ __forceinline__ unsigned long long fma2(unsigned long long a, unsigned long long b,
                                                   unsigned long long c) {
    unsigned long long r;
    asm("fma.rn.f32x2 %0, %1, %2, %3;" : "=l"(r) : "l"(a), "l"(b), "l"(c));
    return r;
}

__device__ __forceinline__ void mbar_init(unsigned mbar, unsigned count) {
    asm volatile("mbarrier.init.shared.b64 [%0], %1;" :: "r"(mbar), "r"(count) : "memory");
}

__device__ __forceinline__ void mbar_expect_tx(unsigned mbar, unsigned bytes) {
    asm volatile("mbarrier.arrive.expect_tx.shared.b64 _, [%0], %1;"
                 :: "r"(mbar), "r"(bytes) : "memory");
}

__device__ __forceinline__ void mbar_wait(unsigned mbar, unsigned parity) {
    asm volatile(
        "{\n\t"
        ".reg .pred P1;\n\t"
        "WAIT_LOOP_%=:\n\t"
        "mbarrier.try_wait.parity.acquire.cta.shared::cta.b64 P1, [%0], %1, 0x989680;\n\t"
        "@P1 bra.uni WAIT_DONE_%=;\n\t"
        "bra.uni WAIT_LOOP_%=;\n\t"
        "WAIT_DONE_%=:\n\t"
        "}"
        :: "r"(mbar), "r"(parity) : "memory");
}

__device__ __forceinline__ void bulk_cp(unsigned sdst, const void* gsrc,
                                        unsigned bytes, unsigned mbar) {
    asm volatile(
        "cp.async.bulk.shared::cta.global.mbarrier::complete_tx::bytes [%0], [%1], %2, [%3];"
        :: "r"(sdst), "l"(gsrc), "r"(bytes), "r"(mbar) : "memory");
}

__device__ __forceinline__ void group_bar(int gid) {
    asm volatile("bar.sync %0, %1;" :: "r"(gid + 1), "r"(128) : "memory");
}

__device__ __forceinline__ void issue_stage_bulk(unsigned sdst, long z, unsigned mbar,
                                                 const float* __restrict__ x0,
                                                 const float* __restrict__ x1,
                                                 const float* __restrict__ x2) {
    mbar_expect_tx(mbar, TILE_BYTES);
    bulk_cp(sdst,              x0 + z * SU, SU * 4, mbar);
    bulk_cp(sdst + SU * 4,     x1 + z * SU, SU * 4, mbar);
    bulk_cp(sdst + 2 * SU * 4, x2 + z * SU, SU * 4, mbar);
}

__global__ __launch_bounds__(NTHREADS, 2)
void ftp4_kernel(const float* __restrict__ x0,
                 const float* __restrict__ x1,
                 const float* __restrict__ x2,
                 const int* __restrict__ path_indices,
                 const float* __restrict__ path_coeff,
                 float* __restrict__ out,
                 int Z, int P) {
    extern __shared__ float smem[];   // [GROUPS][2][TILE] then 8 mbarriers

    // Per-block prep results + scratch (static shared).
    __shared__ uint4 smeta[P_MAX + 1];       // +1 pad so prefetch past end is safe
    __shared__ int   sqnj[4];
    __shared__ int   sqjoff[4][S_SEG];
    __shared__ int   sqstartg[4][S_SEG + 1];
    __shared__ int   sidx[P_MAX * 4];
    __shared__ float scf[P_MAX];
    __shared__ int   sjlist[S_SEG][P_MAX];
    __shared__ int   skeys[S_SEG][P_MAX];
    __shared__ int   scnt[S_SEG];
    __shared__ int   sgj[S_SEG];
    __shared__ int   sgstart[S_SEG + 1];
    __shared__ int   sqstart[4];

    const int tid = threadIdx.x;
    const int ws = tid >> 5;
    const int g = ws >> 2;            // group / z-stream 0..3
    const int q = ws & 3;             // j-quarter for this warp
    const int lane = tid & 31;
    const int gt = tid & 127;

    const unsigned smbase = smem_u32(smem);
    const unsigned sb0 = smbase + (unsigned)g * (2 * TILE_BYTES);
    const unsigned sb1 = sb0 + TILE_BYTES;
    const unsigned mbar_base = smbase + (unsigned)(GROUPS * 2 * TILE_BYTES);
    const unsigned mb0 = mbar_base + (unsigned)g * 16;
    const unsigned mb1 = mb0 + 8;
    const unsigned smeta_base = smem_u32(smeta);

    if (tid < GROUPS * 2) mbar_init(mbar_base + tid * 8, 1);
    __syncthreads();

    const int stream = blockIdx.x * GROUPS + g;
    const int stride = GRID_BLOCKS * GROUPS;            // 1184
    const int nz = (Z > stream) ? ((Z - 1 - stream) / stride + 1) : 0;

    // Kick off buffer-0 staging first so TMA overlaps the prep below.
    if (gt == 0 && nz > 0) issue_stage_bulk(sb0, (long)stream, mb0, x0, x1, x2);

    // ---- Per-block prep (warp 0), identical in every block.
    if (ws == 0) {
        const int t = lane;
        for (int i = t; i < P * 4; i += 32) sidx[i] = path_indices[i];
        for (int i = t; i < P; i += 32) scf[i] = path_coeff[i];
        if (t == 0) smeta[P_MAX] = make_uint4(0, 0, 0, 0);   // prefetch pad
        __syncwarp();

        // Phase B: per-j gather + column priority + sort (8 lanes in parallel).
        if (t < S_SEG) {
            const int j = t;
            unsigned m0 = 0, m1 = 0, m2 = 0;
            int n = 0;
            for (int p = 0; p < P; p++) {
                if (sidx[p * 4 + 3] == j) {
                    sjlist[j][n] = p;
                    n++;
                    m0 |= 1u << sidx[p * 4 + 0];
                    m1 |= 1u << sidx[p * 4 + 1];
                    m2 |= 1u << sidx[p * 4 + 2];
                }
            }
            scnt[j] = n;
            int dc0 = __popc(m0), dc1 = __popc(m1), dc2 = __popc(m2);
            int c0 = 0, c1 = 1, c2 = 2;
            if (dc1 < dc0) { int x = c0; c0 = c1; c1 = x; int y = dc0; dc0 = dc1; dc1 = y; }
            if (dc2 < dc0) { int x = c0; c0 = c2; c2 = x; int y = dc0; dc0 = dc2; dc2 = y; }
            if (dc2 < dc1) { int x = c1; c1 = c2; c2 = x; int y = dc1; dc1 = dc2; dc2 = y; }
            for (int e = 0; e < n; e++) {
                int id = sjlist[j][e];
                skeys[j][e] = (sidx[id * 4 + c0] << 6) | (sidx[id * 4 + c1] << 3) |
                              sidx[id * 4 + c2];
            }
            for (int e = 1; e < n; e++) {
                int id = sjlist[j][e];
                int key = skeys[j][e];
                int f = e - 1;
                while (f >= 0 && skeys[j][f] > key) {
                    skeys[j][f + 1] = skeys[j][f];
                    sjlist[j][f + 1] = sjlist[j][f];
                    f--;
                }
                skeys[j][f + 1] = key;
                sjlist[j][f + 1] = id;
            }
        }
        __syncwarp();

        // Phase C: layout (lane 0).
        if (t == 0) {
            int ord[S_SEG];
#pragma unroll
            for (int j = 0; j < S_SEG; j++) ord[j] = j;
#pragma unroll
            for (int a = 0; a < S_SEG; a++)
#pragma unroll
                for (int b = a + 1; b < S_SEG; b++)
                    if (scnt[ord[b]] > scnt[ord[a]]) { int x = ord[a]; ord[a] = ord[b]; ord[b] = x; }

            int qsum[4] = {0, 0, 0, 0};
            int qnj[4] = {0, 0, 0, 0};
            int qjv[4][S_SEG];
#pragma unroll
            for (int a = 0; a < S_SEG; a++) {
                int qq = 0, best = qsum[0];
                if (qsum[1] < best) { qq = 1; best = qsum[1]; }
                if (qsum[2] < best) { qq = 2; best = qsum[2]; }
                if (qsum[3] < best) { qq = 3; best = qsum[3]; }
                qjv[qq][qnj[qq]] = ord[a];
                qnj[qq]++;
                qsum[qq] += scnt[ord[a]];
            }

            int pos = 0, gidx = 0;
            for (int qq = 0; qq < 4; qq++) {
                sqnj[qq] = qnj[qq];
                sqstart[qq] = pos;
                for (int tt = 0; tt < qnj[qq]; tt++) {
                    int j = qjv[qq][tt];
                    sqjoff[qq][tt] = j * U_CH * 4;
                    sqstartg[qq][tt] = pos;
                    sgj[gidx] = j;
                    sgstart[gidx] = pos;
                    pos += scnt[j];
                    sqstartg[qq][tt + 1] = pos;
                    gidx++;
                }
                for (int tt = qnj[qq]; tt < S_SEG; tt++) {
                    sqjoff[qq][tt] = 0;
                    sqstartg[qq][tt + 1] = pos;
                }
            }
            sgstart[S_SEG] = pos;   // == P
        }
        __syncwarp();

        // Phase D: parallel meta emission with reuse flags.
        for (int e = t; e < P; e += 32) {
            int gidx = 0;
#pragma unroll
            for (int gg = 1; gg < S_SEG; gg++) if (e >= sgstart[gg]) gidx = gg;
            const int j = sgj[gidx];
            const int id = sjlist[j][e - sgstart[gidx]];
            const int i0 = sidx[id * 4 + 0];
            const int i1 = sidx[id * 4 + 1];
            const int i2 = sidx[id * 4 + 2];

            const bool qs = (e == sqstart[0]) | (e == sqstart[1]) |
                            (e == sqstart[2]) | (e == sqstart[3]);
            unsigned f0 = 0, f1 = 0, f2 = 0;
            if (!qs) {
                int g2 = 0;
#pragma unroll
                for (int gg = 1; gg < S_SEG; gg++) if (e - 1 >= sgstart[gg]) g2 = gg;
                const int j2 = sgj[g2];
                const int id2 = sjlist[j2][e - 1 - sgstart[g2]];
                f0 = (i0 == sidx[id2 * 4 + 0]) ? 1u : 0u;
                f1 = (i1 == sidx[id2 * 4 + 1]) ? 1u : 0u;
                f2 = (i2 == sidx[id2 * 4 + 2]) ? 1u : 0u;
            }
            uint4 m;
            m.x = (unsigned)((0 * S_SEG + i0) * U_CH * 4) | f0;
            m.y = (unsigned)((1 * S_SEG + i1) * U_CH * 4) | f1;
            m.z = (unsigned)((2 * S_SEG + i2) * U_CH * 4) | f2;
            m.w = __float_as_uint(scf[id]);
            smeta[e] = m;
        }
    }
    __syncthreads();   // prep visible to all warps

    if (nz == 0) return;

    const int nj = sqnj[q];

    // Operand registers persist across paths/groups (reuse chain per quarter per z).
    unsigned long long va0 = 0, va1 = 0, vb0 = 0, vb1 = 0, vc0 = 0, vc1 = 0;

    for (int k = 0; k < nz; k++) {
        const long z = (long)stream + (long)k * stride;
        const int b = k & 1;
        const unsigned scur = b ? sb1 : sb0;

        if (k + 1 < nz && gt == 0)
            issue_stage_bulk(b ? sb0 : sb1, z + stride, b ? mb0 : mb1, x0, x1, x2);

        mbar_wait(b ? mb1 : mb0, (unsigned)((k >> 1) & 1));

        const unsigned sbase = scur + (unsigned)(lane * 16);
        char* ozb = (char*)(out + z * SU + lane * 4);

        for (int t = 0; t < nj; t++) {
            const int joff = sqjoff[q][t];
            const int pb = sqstartg[q][t];
            const int pe = sqstartg[q][t + 1];
            unsigned long long accA = 0ull, accB = 0ull;

            // Software-pipelined meta: m holds meta[p]; prefetch meta[p+1]
            // at iteration top so the data-LDS address chain has a full
            // iteration of slack (meta is contiguous; array padded by 1).
            unsigned mp = smeta_base + (unsigned)pb * 16;
            uint4 m;
            ldsv4(m, mp);
            for (int p = pb; p < pe; p++) {
                uint4 mn;
                ldsv4(mn, mp + 16);
                mp += 16;
                lds128_cond(va0, va1, sbase, m.x);
                lds128_cond(vb0, vb1, sbase, m.y);
                lds128_cond(vc0, vc1, sbase, m.z);
                unsigned long long cc;
                asm("mov.b64 %0, {%1, %1};" : "=l"(cc) : "r"(m.w));
                unsigned long long t0 = mul2(va0, vb0);
                unsigned long long t1 = mul2(va1, vb1);
                t0 = mul2(t0, vc0);
                t1 = mul2(t1, vc1);
                accA = fma2(t0, cc, accA);
                accB = fma2(t1, cc, accB);
                m = mn;
            }

            unsigned r0, r1, r2, r3;
            asm("mov.b64 {%0, %1}, %2;" : "=r"(r0), "=r"(r1) : "l"(accA));
            asm("mov.b64 {%0, %1}, %2;" : "=r"(r2), "=r"(r3) : "l"(accB));
            float4 r;
            r.x = __uint_as_float(r0);
            r.y = __uint_as_float(r1);
            r.z = __uint_as_float(r2);
            r.w = __uint_as_float(r3);
            *(float4*)(ozb + joff) = r;
        }

        group_bar(g);   // all readers of this buffer done before it is re-staged
    }
}

extern "C" void kernel_launch(void* const* d_in, const int* in_sizes, int n_in,
                              void* d_out, int out_size) {
    const float* x0 = (const float*)d_in[0];
    const float* x1 = (const float*)d_in[1];
    const float* x2 = (const float*)d_in[2];
    const float* coeff = (const float*)d_in[3];
    const int*   pidx = (const int*)d_in[4];
    float* out = (float*)d_out;

    const int P = in_sizes[3];            // 64
    const int Z = in_sizes[0] / SU;       // 20000

    const size_t smem_bytes = (size_t)GROUPS * 2 * TILE_BYTES + GROUPS * 2 * 8 + 64;

    static bool attr_set = false;
    if (!attr_set) {
        cudaFuncSetAttribute(ftp4_kernel,
                             cudaFuncAttributeMaxDynamicSharedMemorySize,
                             (int)smem_bytes);
        attr_set = true;
    }

    ftp4_kernel<<<GRID_BLOCKS, NTHREADS, smem_bytes>>>(x0, x1, x2, pidx, coeff,
                                                       out, Z, P);
}

// round 16
// speedup vs baseline: 1.0521x; 1.0521x over previous
#include <cuda_runtime.h>
#include <cstdint>

#define S_SEG 8
#define U_CH 128
#define SU 1024                 // S_SEG * U_CH
#define P_MAX 64
#define GROUPS 4                // z-streams per block (128 threads each)
#define NTHREADS 512
#define TILE_FLOATS (3 * S_SEG * U_CH)   // 3072 floats = 12 KB
#define TILE_BYTES (TILE_FLOATS * 4)     // 12288
#define GRID_BLOCKS 296         // 2 per SM

// j-groups partitioned 4 ways; paths sorted within groups for operand reuse;
// bit0 of each offset = "same operand as previous path in this quarter" flag.
struct PrepData {
    uint4 meta[P_MAX];           // {off0|f0, off1|f1, off2|f2, coeff_bits}
    int   qnj[4];                // #j-groups per quarter
    int   qjoff[4][S_SEG];       // output byte offset per group
    int   qstart[4][S_SEG + 1];  // path-range per group
};

// Main kernel reads meta via the constant port (proven critical: R3 & R14).
// The prep kernel writes DIRECTLY to this symbol's backing store (device
// address obtained host-side via cudaGetSymbolAddress) — no memcpy node.
// Safe: graph edge orders prep before main; prep is deterministic, so every
// replay writes identical bytes.
__constant__ PrepData c_prep;

__global__ void prep_kernel(const int* __restrict__ path_indices,
                            const float* __restrict__ path_coeff,
                            int P, PrepData* __restrict__ outp) {
    __shared__ int   sidx[P_MAX * 4];
    __shared__ float scf[P_MAX];
    __shared__ int   sjlist[S_SEG][P_MAX];   // sorted path ids per j
    __shared__ int   skeys[S_SEG][P_MAX];    // sort keys per j
    __shared__ int   scnt[S_SEG];            // paths per j
    __shared__ int   sgj[S_SEG];             // emission-order group -> j
    __shared__ int   sgstart[S_SEG + 1];     // emission-order group start pos
    __shared__ int   sqstart[4];             // quarter start positions
    __shared__ int   sqj[4][S_SEG];          // quarter -> j list
    __shared__ int   sqnj[4];

    const int t = threadIdx.x;
    for (int i = t; i < P * 4; i += 32) sidx[i] = path_indices[i];
    for (int i = t; i < P; i += 32) scf[i] = path_coeff[i];
    __syncwarp();

    // ---- Phase B: per-j gather + column-priority + sort, 8 lanes in parallel.
    if (t < S_SEG) {
        const int j = t;
        unsigned m0 = 0, m1 = 0, m2 = 0;
        int n = 0;
        for (int p = 0; p < P; p++) {
            if (sidx[p * 4 + 3] == j) {
                sjlist[j][n] = p;
                n++;
                m0 |= 1u << sidx[p * 4 + 0];
                m1 |= 1u << sidx[p * 4 + 1];
                m2 |= 1u << sidx[p * 4 + 2];
            }
        }
        scnt[j] = n;
        int dc0 = __popc(m0), dc1 = __popc(m1), dc2 = __popc(m2);
        int c0 = 0, c1 = 1, c2 = 2;
        if (dc1 < dc0) { int x = c0; c0 = c1; c1 = x; int y = dc0; dc0 = dc1; dc1 = y; }
        if (dc2 < dc0) { int x = c0; c0 = c2; c2 = x; int y = dc0; dc0 = dc2; dc2 = y; }
        if (dc2 < dc1) { int x = c1; c1 = c2; c2 = x; int y = dc1; dc1 = dc2; dc2 = y; }
        for (int e = 0; e < n; e++) {
            int id = sjlist[j][e];
            skeys[j][e] = (sidx[id * 4 + c0] << 6) | (sidx[id * 4 + c1] << 3) |
                          sidx[id * 4 + c2];
        }
        // Stable insertion sort (keys + ids move together).
        for (int e = 1; e < n; e++) {
            int id = sjlist[j][e];
            int key = skeys[j][e];
            int f = e - 1;
            while (f >= 0 && skeys[j][f] > key) {
                skeys[j][f + 1] = skeys[j][f];
                sjlist[j][f + 1] = sjlist[j][f];
                f--;
            }
            skeys[j][f + 1] = key;
            sjlist[j][f + 1] = id;
        }
    }
    __syncwarp();

    // ---- Phase C: layout (thread 0; ~100 small ops).
    if (t == 0) {
        int ord[S_SEG];
#pragma unroll
        for (int j = 0; j < S_SEG; j++) ord[j] = j;
#pragma unroll
        for (int a = 0; a < S_SEG; a++)
#pragma unroll
            for (int b = a + 1; b < S_SEG; b++)
                if (scnt[ord[b]] > scnt[ord[a]]) { int x = ord[a]; ord[a] = ord[b]; ord[b] = x; }

        int qsum0 = 0, qsum1 = 0, qsum2 = 0, qsum3 = 0;
        sqnj[0] = 0; sqnj[1] = 0; sqnj[2] = 0; sqnj[3] = 0;
#pragma unroll
        for (int a = 0; a < S_SEG; a++) {
            int q = 0, best = qsum0;
            if (qsum1 < best) { q = 1; best = qsum1; }
            if (qsum2 < best) { q = 2; best = qsum2; }
            if (qsum3 < best) { q = 3; best = qsum3; }
            sqj[q][sqnj[q]] = ord[a];
            sqnj[q]++;
            int c = scnt[ord[a]];
            if (q == 0) qsum0 += c; else if (q == 1) qsum1 += c;
            else if (q == 2) qsum2 += c; else qsum3 += c;
        }

        int pos = 0, gidx = 0;
        for (int q = 0; q < 4; q++) {
            int nq = sqnj[q];
            sqstart[q] = pos;
            outp->qnj[q] = nq;
            for (int tt = 0; tt < nq; tt++) {
                int j = sqj[q][tt];
                outp->qjoff[q][tt] = j * U_CH * 4;
                outp->qstart[q][tt] = pos;
                sgj[gidx] = j;
                sgstart[gidx] = pos;
                pos += scnt[j];
                outp->qstart[q][tt + 1] = pos;
                gidx++;
            }
            for (int tt = nq; tt < S_SEG; tt++) {
                outp->qjoff[q][tt] = 0;
                outp->qstart[q][tt + 1] = pos;
            }
        }
        sgstart[S_SEG] = pos;   // == P
    }
    __syncwarp();

    // ---- Phase D: parallel meta emission with reuse flags.
    for (int e = t; e < P; e += 32) {
        int gidx = 0;
#pragma unroll
        for (int gg = 1; gg < S_SEG; gg++) if (e >= sgstart[gg]) gidx = gg;
        const int j = sgj[gidx];
        const int id = sjlist[j][e - sgstart[gidx]];
        const int i0 = sidx[id * 4 + 0];
        const int i1 = sidx[id * 4 + 1];
        const int i2 = sidx[id * 4 + 2];

        const bool qs = (e == sqstart[0]) | (e == sqstart[1]) |
                        (e == sqstart[2]) | (e == sqstart[3]);
        unsigned f0 = 0, f1 = 0, f2 = 0;
        if (!qs) {
            int g2 = 0;
#pragma unroll
            for (int gg = 1; gg < S_SEG; gg++) if (e - 1 >= sgstart[gg]) g2 = gg;
            const int j2 = sgj[g2];
            const int id2 = sjlist[j2][e - 1 - sgstart[g2]];
            f0 = (i0 == sidx[id2 * 4 + 0]) ? 1u : 0u;
            f1 = (i1 == sidx[id2 * 4 + 1]) ? 1u : 0u;
            f2 = (i2 == sidx[id2 * 4 + 2]) ? 1u : 0u;
        }
        uint4 m;
        m.x = (unsigned)((0 * S_SEG + i0) * U_CH * 4) | f0;
        m.y = (unsigned)((1 * S_SEG + i1) * U_CH * 4) | f1;
        m.z = (unsigned)((2 * S_SEG + i2) * U_CH * 4) | f2;
        m.w = __float_as_uint(scf[id]);
        outp->meta[e] = m;
    }
}

__device__ __forceinline__ unsigned smem_u32(const void* p) {
    unsigned a;
    asm("{ .reg .u64 t; cvta.to.shared.u64 t, %1; cvt.u32.u64 %0, t; }"
        : "=r"(a) : "l"(p));
    return a;
}

// Predicated LDS.128: load only when bit0 of moff is clear (offset is clean then).
__device__ __forceinline__ void lds128_cond(unsigned long long& v0, unsigned long long& v1,
                                            unsigned sbase, unsigned moff) {
    asm volatile(
        "{\n\t"
        ".reg .pred p;\n\t"
        ".reg .u32 f, a;\n\t"
        "and.b32 f, %3, 1;\n\t"
        "setp.eq.u32 p, f, 0;\n\t"
        "add.u32 a, %2, %3;\n\t"
        "@p ld.shared.v2.u64 {%0, %1}, [a];\n\t"
        "}"
        : "+l"(v0), "+l"(v1) : "r"(sbase), "r"(moff));
}

__device__ __forceinline__ unsigned long long mul2(unsigned long long a, unsigned long long b) {
    unsigned long long r;
    asm("mul.rn.f32x2 %0, %1, %2;" : "=l"(r) : "l"(a), "l"(b));
    return r;
}

__device__ __forceinline__ unsigned long long fma2(unsigned long long a, unsigned long long b,
                                                   unsigned long long c) {
    unsigned long long r;
    asm("fma.rn.f32x2 %0, %1, %2, %3;" : "=l"(r) : "l"(a), "l"(b), "l"(c));
    return r;
}

__device__ __forceinline__ unsigned long long add2(unsigned long long a, unsigned long long b) {
    unsigned long long r;
    asm("add.rn.f32x2 %0, %1, %2;" : "=l"(r) : "l"(a), "l"(b));
    return r;
}

__device__ __forceinline__ void mbar_init(unsigned mbar, unsigned count) {
    asm volatile("mbarrier.init.shared.b64 [%0], %1;" :: "r"(mbar), "r"(count) : "memory");
}

__device__ __forceinline__ void mbar_expect_tx(unsigned mbar, unsigned bytes) {
    asm volatile("mbarrier.arrive.expect_tx.shared.b64 _, [%0], %1;"
                 :: "r"(mbar), "r"(bytes) : "memory");
}

__device__ __forceinline__ void mbar_wait(unsigned mbar, unsigned parity) {
    asm volatile(
        "{\n\t"
        ".reg .pred P1;\n\t"
        "WAIT_LOOP_%=:\n\t"
        "mbarrier.try_wait.parity.acquire.cta.shared::cta.b64 P1, [%0], %1, 0x989680;\n\t"
        "@P1 bra.uni WAIT_DONE_%=;\n\t"
        "bra.uni WAIT_LOOP_%=;\n\t"
        "WAIT_DONE_%=:\n\t"
        "}"
        :: "r"(mbar), "r"(parity) : "memory");
}

__device__ __forceinline__ void bulk_cp(unsigned sdst, const void* gsrc,
                                        unsigned bytes, unsigned mbar) {
    asm volatile(
        "cp.async.bulk.shared::cta.global.mbarrier::complete_tx::bytes [%0], [%1], %2, [%3];"
        :: "r"(sdst), "l"(gsrc), "r"(bytes), "r"(mbar) : "memory");
}

__device__ __forceinline__ void group_bar(int gid) {
    asm volatile("bar.sync %0, %1;" :: "r"(gid + 1), "r"(128) : "memory");
}

__device__ __forceinline__ void issue_stage_bulk(unsigned sdst, long z, unsigned mbar,
                                                 const float* __restrict__ x0,
                                                 const float* __restrict__ x1,
                                                 const float* __restrict__ x2) {
    mbar_expect_tx(mbar, TILE_BYTES);
    bulk_cp(sdst,              x0 + z * SU, SU * 4, mbar);
    bulk_cp(sdst + SU * 4,     x1 + z * SU, SU * 4, mbar);
    bulk_cp(sdst + 2 * SU * 4, x2 + z * SU, SU * 4, mbar);
}

__global__ __launch_bounds__(NTHREADS, 2)
void ftp4_kernel(const float* __restrict__ x0,
                 const float* __restrict__ x1,
                 const float* __restrict__ x2,
                 float* __restrict__ out,
                 int Z) {
    extern __shared__ float smem[];   // [GROUPS][2][TILE] then 8 mbarriers

    const int tid = threadIdx.x;
    const int ws = tid >> 5;
    const int g = ws >> 2;            // group / z-stream 0..3
    const int q = ws & 3;             // j-quarter for this warp
    const int lane = tid & 31;
    const int gt = tid & 127;

    const unsigned smbase = smem_u32(smem);
    const unsigned sb0 = smbase + (unsigned)g * (2 * TILE_BYTES);
    const unsigned sb1 = sb0 + TILE_BYTES;
    const unsigned mbar_base = smbase + (unsigned)(GROUPS * 2 * TILE_BYTES);
    const unsigned mb0 = mbar_base + (unsigned)g * 16;
    const unsigned mb1 = mb0 + 8;

    if (tid < GROUPS * 2) mbar_init(mbar_base + tid * 8, 1);
    __syncthreads();

    const int stream = blockIdx.x * GROUPS + g;
    const int stride = GRID_BLOCKS * GROUPS;            // 1184
    const int nz = (Z > stream) ? ((Z - 1 - stream) / stride + 1) : 0;
    if (nz == 0) return;

    if (gt == 0) issue_stage_bulk(sb0, (long)stream, mb0, x0, x1, x2);

    const int nj = c_prep.qnj[q];

    // Operand registers persist across paths/groups (reuse chain per quarter per z).
    unsigned long long va0 = 0, va1 = 0, vb0 = 0, vb1 = 0, vc0 = 0, vc1 = 0;

    for (int k = 0; k < nz; k++) {
        const long z = (long)stream + (long)k * stride;
        const int b = k & 1;
        const unsigned scur = b ? sb1 : sb0;

        if (k + 1 < nz && gt == 0)
            issue_stage_bulk(b ? sb0 : sb1, z + stride, b ? mb0 : mb1, x0, x1, x2);

        mbar_wait(b ? mb1 : mb0, (unsigned)((k >> 1) & 1));

        const unsigned sbase = scur + (unsigned)(lane * 16);
        char* ozb = (char*)(out + z * SU + lane * 4);

        for (int t = 0; t < nj; t++) {
            const int joff = c_prep.qjoff[q][t];
            const int pb = c_prep.qstart[q][t];
            const int pe = c_prep.qstart[q][t + 1];
            unsigned long long a0A = 0ull, a0B = 0ull, a1A = 0ull, a1B = 0ull;
            int p = pb;
            for (; p + 1 < pe; p += 2) {
                {
                    uint4 m = c_prep.meta[p];
                    lds128_cond(va0, va1, sbase, m.x);
                    lds128_cond(vb0, vb1, sbase, m.y);
                    lds128_cond(vc0, vc1, sbase, m.z);
                    unsigned long long cc;
                    asm("mov.b64 %0, {%1, %1};" : "=l"(cc) : "r"(m.w));
                    unsigned long long t0 = mul2(va0, vb0);
                    unsigned long long t1 = mul2(va1, vb1);
                    t0 = mul2(t0, vc0);
                    t1 = mul2(t1, vc1);
                    a0A = fma2(t0, cc, a0A);
                    a0B = fma2(t1, cc, a0B);
                }
                {
                    uint4 m = c_prep.meta[p + 1];
                    lds128_cond(va0, va1, sbase, m.x);
                    lds128_cond(vb0, vb1, sbase, m.y);
                    lds128_cond(vc0, vc1, sbase, m.z);
                    unsigned long long cc;
                    asm("mov.b64 %0, {%1, %1};" : "=l"(cc) : "r"(m.w));
                    unsigned long long t0 = mul2(va0, vb0);
                    unsigned long long t1 = mul2(va1, vb1);
                    t0 = mul2(t0, vc0);
                    t1 = mul2(t1, vc1);
                    a1A = fma2(t0, cc, a1A);
                    a1B = fma2(t1, cc, a1B);
                }
            }
            if (p < pe) {
                uint4 m = c_prep.meta[p];
                lds128_cond(va0, va1, sbase, m.x);
                lds128_cond(vb0, vb1, sbase, m.y);
                lds128_cond(vc0, vc1, sbase, m.z);
                unsigned long long cc;
                asm("mov.b64 %0, {%1, %1};" : "=l"(cc) : "r"(m.w));
                unsigned long long t0 = mul2(va0, vb0);
                unsigned long long t1 = mul2(va1, vb1);
                t0 = mul2(t0, vc0);
                t1 = mul2(t1, vc1);
                a0A = fma2(t0, cc, a0A);
                a0B = fma2(t1, cc, a0B);
            }
            unsigned long long accA = add2(a0A, a1A);
            unsigned long long accB = add2(a0B, a1B);

            unsigned r0, r1, r2, r3;
            asm("mov.b64 {%0, %1}, %2;" : "=r"(r0), "=r"(r1) : "l"(accA));
            asm("mov.b64 {%0, %1}, %2;" : "=r"(r2), "=r"(r3) : "l"(accB));
            float4 r;
            r.x = __uint_as_float(r0);
            r.y = __uint_as_float(r1);
            r.z = __uint_as_float(r2);
            r.w = __uint_as_float(r3);
            *(float4*)(ozb + joff) = r;
        }

        group_bar(g);   // all readers of this buffer done before it is re-staged
    }
}

extern "C" void kernel_launch(void* const* d_in, const int* in_sizes, int n_in,
                              void* d_out, int out_size) {
    const float* x0 = (const float*)d_in[0];
    const float* x1 = (const float*)d_in[1];
    const float* x2 = (const float*)d_in[2];
    const float* coeff = (const float*)d_in[3];
    const int*   pidx = (const int*)d_in[4];
    float* out = (float*)d_out;

    const int P = in_sizes[3];            // 64
    const int Z = in_sizes[0] / SU;       // 20000

    // Device address of the __constant__ symbol's backing store; prep writes
    // it directly (replaces the memcpyToSymbol graph node).
    static PrepData* c_prep_dev = nullptr;
    static bool attr_set = false;
    const size_t smem_bytes = (size_t)GROUPS * 2 * TILE_BYTES + GROUPS * 2 * 8 + 64;
    if (!attr_set) {
        void* a = nullptr;
        cudaGetSymbolAddress(&a, c_prep);
        c_prep_dev = (PrepData*)a;
        cudaFuncSetAttribute(ftp4_kernel,
                             cudaFuncAttributeMaxDynamicSharedMemorySize,
                             (int)smem_bytes);
        attr_set = true;
    }

    prep_kernel<<<1, 32>>>(pidx, coeff, P, c_prep_dev);
    ftp4_kernel<<<GRID_BLOCKS, NTHREADS, smem_bytes>>>(x0, x1, x2, out, Z);
}

// round 17
// speedup vs baseline: 1.0569x; 1.0045x over previous
#include <cuda_runtime.h>
#include <cstdint>

#define S_SEG 8
#define U_CH 128
#define SU 1024                 // S_SEG * U_CH
#define P_MAX 64
#define GROUPS 4                // z-streams per block (128 threads each)
#define NTHREADS 512
#define TILE_FLOATS (3 * S_SEG * U_CH)   // 3072 floats = 12 KB
#define TILE_BYTES (TILE_FLOATS * 4)     // 12288
#define GRID_BLOCKS 296         // 2 per SM

// j-groups partitioned 4 ways; paths sorted within groups for operand reuse;
// bit0 of each offset = "same operand as previous path in this quarter" flag.
struct PrepData {
    uint4 meta[P_MAX];           // {off0|f0, off1|f1, off2|f2, coeff_bits}
    int   qnj[4];                // #j-groups per quarter
    int   qjoff[4][S_SEG];       // output byte offset per group
    int   qstart[4][S_SEG + 1];  // path-range per group
};

// Main kernel reads meta via the constant port (proven critical: R3/R14/R16).
// Prep writes DIRECTLY to this symbol's backing store; PDL's grid-dependency
// sync orders those writes before main's (cold, demand-filled) LDC reads.
__constant__ PrepData c_prep;

__global__ void prep_kernel(const int* __restrict__ path_indices,
                            const float* __restrict__ path_coeff,
                            int P, PrepData* __restrict__ outp) {
    // Let the dependent kernel start launching immediately; its
    // cudaGridDependencySynchronize() still waits for our completion.
    cudaTriggerProgrammaticLaunchCompletion();

    __shared__ int   sidx[P_MAX * 4];
    __shared__ float scf[P_MAX];
    __shared__ int   sjlist[S_SEG][P_MAX];   // sorted path ids per j
    __shared__ int   skeys[S_SEG][P_MAX];    // sort keys per j
    __shared__ int   scnt[S_SEG];            // paths per j
    __shared__ int   sgj[S_SEG];             // emission-order group -> j
    __shared__ int   sgstart[S_SEG + 1];     // emission-order group start pos
    __shared__ int   sqstart[4];             // quarter start positions
    __shared__ int   sqj[4][S_SEG];          // quarter -> j list
    __shared__ int   sqnj[4];

    const int t = threadIdx.x;
    for (int i = t; i < P * 4; i += 32) sidx[i] = path_indices[i];
    for (int i = t; i < P; i += 32) scf[i] = path_coeff[i];
    __syncwarp();

    // ---- Phase B: per-j gather + column-priority + sort, 8 lanes in parallel.
    if (t < S_SEG) {
        const int j = t;
        unsigned m0 = 0, m1 = 0, m2 = 0;
        int n = 0;
        for (int p = 0; p < P; p++) {
            if (sidx[p * 4 + 3] == j) {
                sjlist[j][n] = p;
                n++;
                m0 |= 1u << sidx[p * 4 + 0];
                m1 |= 1u << sidx[p * 4 + 1];
                m2 |= 1u << sidx[p * 4 + 2];
            }
        }
        scnt[j] = n;
        int dc0 = __popc(m0), dc1 = __popc(m1), dc2 = __popc(m2);
        int c0 = 0, c1 = 1, c2 = 2;
        if (dc1 < dc0) { int x = c0; c0 = c1; c1 = x; int y = dc0; dc0 = dc1; dc1 = y; }
        if (dc2 < dc0) { int x = c0; c0 = c2; c2 = x; int y = dc0; dc0 = dc2; dc2 = y; }
        if (dc2 < dc1) { int x = c1; c1 = c2; c2 = x; int y = dc1; dc1 = dc2; dc2 = y; }
        for (int e = 0; e < n; e++) {
            int id = sjlist[j][e];
            skeys[j][e] = (sidx[id * 4 + c0] << 6) | (sidx[id * 4 + c1] << 3) |
                          sidx[id * 4 + c2];
        }
        // Stable insertion sort (keys + ids move together).
        for (int e = 1; e < n; e++) {
            int id = sjlist[j][e];
            int key = skeys[j][e];
            int f = e - 1;
            while (f >= 0 && skeys[j][f] > key) {
                skeys[j][f + 1] = skeys[j][f];
                sjlist[j][f + 1] = sjlist[j][f];
                f--;
            }
            skeys[j][f + 1] = key;
            sjlist[j][f + 1] = id;
        }
    }
    __syncwarp();

    // ---- Phase C: layout (thread 0; ~100 small ops).
    if (t == 0) {
        int ord[S_SEG];
#pragma unroll
        for (int j = 0; j < S_SEG; j++) ord[j] = j;
#pragma unroll
        for (int a = 0; a < S_SEG; a++)
#pragma unroll
            for (int b = a + 1; b < S_SEG; b++)
                if (scnt[ord[b]] > scnt[ord[a]]) { int x = ord[a]; ord[a] = ord[b]; ord[b] = x; }

        int qsum0 = 0, qsum1 = 0, qsum2 = 0, qsum3 = 0;
        sqnj[0] = 0; sqnj[1] = 0; sqnj[2] = 0; sqnj[3] = 0;
#pragma unroll
        for (int a = 0; a < S_SEG; a++) {
            int q = 0, best = qsum0;
            if (qsum1 < best) { q = 1; best = qsum1; }
            if (qsum2 < best) { q = 2; best = qsum2; }
            if (qsum3 < best) { q = 3; best = qsum3; }
            sqj[q][sqnj[q]] = ord[a];
            sqnj[q]++;
            int c = scnt[ord[a]];
            if (q == 0) qsum0 += c; else if (q == 1) qsum1 += c;
            else if (q == 2) qsum2 += c; else qsum3 += c;
        }

        int pos = 0, gidx = 0;
        for (int q = 0; q < 4; q++) {
            int nq = sqnj[q];
            sqstart[q] = pos;
            outp->qnj[q] = nq;
            for (int tt = 0; tt < nq; tt++) {
                int j = sqj[q][tt];
                outp->qjoff[q][tt] = j * U_CH * 4;
                outp->qstart[q][tt] = pos;
                sgj[gidx] = j;
                sgstart[gidx] = pos;
                pos += scnt[j];
                outp->qstart[q][tt + 1] = pos;
                gidx++;
            }
            for (int tt = nq; tt < S_SEG; tt++) {
                outp->qjoff[q][tt] = 0;
                outp->qstart[q][tt + 1] = pos;
            }
        }
        sgstart[S_SEG] = pos;   // == P
    }
    __syncwarp();

    // ---- Phase D: parallel meta emission with reuse flags.
    for (int e = t; e < P; e += 32) {
        int gidx = 0;
#pragma unroll
        for (int gg = 1; gg < S_SEG; gg++) if (e >= sgstart[gg]) gidx = gg;
        const int j = sgj[gidx];
        const int id = sjlist[j][e - sgstart[gidx]];
        const int i0 = sidx[id * 4 + 0];
        const int i1 = sidx[id * 4 + 1];
        const int i2 = sidx[id * 4 + 2];

        const bool qs = (e == sqstart[0]) | (e == sqstart[1]) |
                        (e == sqstart[2]) | (e == sqstart[3]);
        unsigned f0 = 0, f1 = 0, f2 = 0;
        if (!qs) {
            int g2 = 0;
#pragma unroll
            for (int gg = 1; gg < S_SEG; gg++) if (e - 1 >= sgstart[gg]) g2 = gg;
            const int j2 = sgj[g2];
            const int id2 = sjlist[j2][e - 1 - sgstart[g2]];
            f0 = (i0 == sidx[id2 * 4 + 0]) ? 1u : 0u;
            f1 = (i1 == sidx[id2 * 4 + 1]) ? 1u : 0u;
            f2 = (i2 == sidx[id2 * 4 + 2]) ? 1u : 0u;
        }
        uint4 m;
        m.x = (unsigned)((0 * S_SEG + i0) * U_CH * 4) | f0;
        m.y = (unsigned)((1 * S_SEG + i1) * U_CH * 4) | f1;
        m.z = (unsigned)((2 * S_SEG + i2) * U_CH * 4) | f2;
        m.w = __float_as_uint(scf[id]);
        outp->meta[e] = m;
    }
}

__device__ __forceinline__ unsigned smem_u32(const void* p) {
    unsigned a;
    asm("{ .reg .u64 t; cvta.to.shared.u64 t, %1; cvt.u32.u64 %0, t; }"
        : "=r"(a) : "l"(p));
    return a;
}

// Predicated LDS.128: load only when bit0 of moff is clear (offset is clean then).
__device__ __forceinline__ void lds128_cond(unsigned long long& v0, unsigned long long& v1,
                                            unsigned sbase, unsigned moff) {
    asm volatile(
        "{\n\t"
        ".reg .pred p;\n\t"
        ".reg .u32 f, a;\n\t"
        "and.b32 f, %3, 1;\n\t"
        "setp.eq.u32 p, f, 0;\n\t"
        "add.u32 a, %2, %3;\n\t"
        "@p ld.shared.v2.u64 {%0, %1}, [a];\n\t"
        "}"
        : "+l"(v0), "+l"(v1) : "r"(sbase), "r"(moff));
}

__device__ __forceinline__ unsigned long long mul2(unsigned long long a, unsigned long long b) {
    unsigned long long r;
    asm("mul.rn.f32x2 %0, %1, %2;" : "=l"(r) : "l"(a), "l"(b));
    return r;
}

__device__ __forceinline__ unsigned long long fma2(unsigned long long a, unsigned long long b,
                                                   unsigned long long c) {
    unsigned long long r;
    asm("fma.rn.f32x2 %0, %1, %2, %3;" : "=l"(r) : "l"(a), "l"(b), "l"(c));
    return r;
}

__device__ __forceinline__ unsigned long long add2(unsigned long long a, unsigned long long b) {
    unsigned long long r;
    asm("add.rn.f32x2 %0, %1, %2;" : "=l"(r) : "l"(a), "l"(b));
    return r;
}

__device__ __forceinline__ void mbar_init(unsigned mbar, unsigned count) {
    asm volatile("mbarrier.init.shared.b64 [%0], %1;" :: "r"(mbar), "r"(count) : "memory");
}

__device__ __forceinline__ void mbar_expect_tx(unsigned mbar, unsigned bytes) {
    asm volatile("mbarrier.arrive.expect_tx.shared.b64 _, [%0], %1;"
                 :: "r"(mbar), "r"(bytes) : "memory");
}

__device__ __forceinline__ void mbar_wait(unsigned mbar, unsigned parity) {
    asm volatile(
        "{\n\t"
        ".reg .pred P1;\n\t"
        "WAIT_LOOP_%=:\n\t"
        "mbarrier.try_wait.parity.acquire.cta.shared::cta.b64 P1, [%0], %1, 0x989680;\n\t"
        "@P1 bra.uni WAIT_DONE_%=;\n\t"
        "bra.uni WAIT_LOOP_%=;\n\t"
        "WAIT_DONE_%=:\n\t"
        "}"
        :: "r"(mbar), "r"(parity) : "memory");
}

__device__ __forceinline__ void bulk_cp(unsigned sdst, const void* gsrc,
                                        unsigned bytes, unsigned mbar) {
    asm volatile(
        "cp.async.bulk.shared::cta.global.mbarrier::complete_tx::bytes [%0], [%1], %2, [%3];"
        :: "r"(sdst), "l"(gsrc), "r"(bytes), "r"(mbar) : "memory");
}

__device__ __forceinline__ void group_bar(int gid) {
    asm volatile("bar.sync %0, %1;" :: "r"(gid + 1), "r"(128) : "memory");
}

__device__ __forceinline__ void issue_stage_bulk(unsigned sdst, long z, unsigned mbar,
                                                 const float* __restrict__ x0,
                                                 const float* __restrict__ x1,
                                                 const float* __restrict__ x2) {
    mbar_expect_tx(mbar, TILE_BYTES);
    bulk_cp(sdst,              x0 + z * SU, SU * 4, mbar);
    bulk_cp(sdst + SU * 4,     x1 + z * SU, SU * 4, mbar);
    bulk_cp(sdst + 2 * SU * 4, x2 + z * SU, SU * 4, mbar);
}

__global__ __launch_bounds__(NTHREADS, 2)
void ftp4_kernel(const float* __restrict__ x0,
                 const float* __restrict__ x1,
                 const float* __restrict__ x2,
                 float* __restrict__ out,
                 int Z) {
    extern __shared__ float smem[];   // [GROUPS][2][TILE] then 8 mbarriers

    const int tid = threadIdx.x;
    const int ws = tid >> 5;
    const int g = ws >> 2;            // group / z-stream 0..3
    const int q = ws & 3;             // j-quarter for this warp
    const int lane = tid & 31;
    const int gt = tid & 127;

    const unsigned smbase = smem_u32(smem);
    const unsigned sb0 = smbase + (unsigned)g * (2 * TILE_BYTES);
    const unsigned sb1 = sb0 + TILE_BYTES;
    const unsigned mbar_base = smbase + (unsigned)(GROUPS * 2 * TILE_BYTES);
    const unsigned mb0 = mbar_base + (unsigned)g * 16;
    const unsigned mb1 = mb0 + 8;

    if (tid < GROUPS * 2) mbar_init(mbar_base + tid * 8, 1);
    __syncthreads();

    const int stream = blockIdx.x * GROUPS + g;
    const int stride = GRID_BLOCKS * GROUPS;            // 1184
    const int nz = (Z > stream) ? ((Z - 1 - stream) / stride + 1) : 0;

    // Stage-0 TMA does not depend on prep — issue it before the grid-dep sync
    // so staging overlaps prep's tail.
    if (gt == 0 && nz > 0) issue_stage_bulk(sb0, (long)stream, mb0, x0, x1, x2);

    // Wait for prep_kernel's completion (PDL). After this, its STGs to the
    // c_prep backing store are visible; our constant cache fills on demand.
    cudaGridDependencySynchronize();

    if (nz == 0) return;

    const int nj = c_prep.qnj[q];

    // Operand registers persist across paths/groups (reuse chain per quarter per z).
    unsigned long long va0 = 0, va1 = 0, vb0 = 0, vb1 = 0, vc0 = 0, vc1 = 0;

    for (int k = 0; k < nz; k++) {
        const long z = (long)stream + (long)k * stride;
        const int b = k & 1;
        const unsigned scur = b ? sb1 : sb0;

        if (k + 1 < nz && gt == 0)
            issue_stage_bulk(b ? sb0 : sb1, z + stride, b ? mb0 : mb1, x0, x1, x2);

        mbar_wait(b ? mb1 : mb0, (unsigned)((k >> 1) & 1));

        const unsigned sbase = scur + (unsigned)(lane * 16);
        char* ozb = (char*)(out + z * SU + lane * 4);

        for (int t = 0; t < nj; t++) {
            const int joff = c_prep.qjoff[q][t];
            const int pb = c_prep.qstart[q][t];
            const int pe = c_prep.qstart[q][t + 1];
            unsigned long long a0A = 0ull, a0B = 0ull, a1A = 0ull, a1B = 0ull;
            int p = pb;
            for (; p + 1 < pe; p += 2) {
                {
                    uint4 m = c_prep.meta[p];
                    lds128_cond(va0, va1, sbase, m.x);
                    lds128_cond(vb0, vb1, sbase, m.y);
                    lds128_cond(vc0, vc1, sbase, m.z);
                    unsigned long long cc;
                    asm("mov.b64 %0, {%1, %1};" : "=l"(cc) : "r"(m.w));
                    unsigned long long t0 = mul2(va0, vb0);
                    unsigned long long t1 = mul2(va1, vb1);
                    t0 = mul2(t0, vc0);
                    t1 = mul2(t1, vc1);
                    a0A = fma2(t0, cc, a0A);
                    a0B = fma2(t1, cc, a0B);
                }
                {
                    uint4 m = c_prep.meta[p + 1];
                    lds128_cond(va0, va1, sbase, m.x);
                    lds128_cond(vb0, vb1, sbase, m.y);
                    lds128_cond(vc0, vc1, sbase, m.z);
                    unsigned long long cc;
                    asm("mov.b64 %0, {%1, %1};" : "=l"(cc) : "r"(m.w));
                    unsigned long long t0 = mul2(va0, vb0);
                    unsigned long long t1 = mul2(va1, vb1);
                    t0 = mul2(t0, vc0);
                    t1 = mul2(t1, vc1);
                    a1A = fma2(t0, cc, a1A);
                    a1B = fma2(t1, cc, a1B);
                }
            }
            if (p < pe) {
                uint4 m = c_prep.meta[p];
                lds128_cond(va0, va1, sbase, m.x);
                lds128_cond(vb0, vb1, sbase, m.y);
                lds128_cond(vc0, vc1, sbase, m.z);
                unsigned long long cc;
                asm("mov.b64 %0, {%1, %1};" : "=l"(cc) : "r"(m.w));
                unsigned long long t0 = mul2(va0, vb0);
                unsigned long long t1 = mul2(va1, vb1);
                t0 = mul2(t0, vc0);
                t1 = mul2(t1, vc1);
                a0A = fma2(t0, cc, a0A);
                a0B = fma2(t1, cc, a0B);
            }
            unsigned long long accA = add2(a0A, a1A);
            unsigned long long accB = add2(a0B, a1B);

            unsigned r0, r1, r2, r3;
            asm("mov.b64 {%0, %1}, %2;" : "=r"(r0), "=r"(r1) : "l"(accA));
            asm("mov.b64 {%0, %1}, %2;" : "=r"(r2), "=r"(r3) : "l"(accB));
            float4 r;
            r.x = __uint_as_float(r0);
            r.y = __uint_as_float(r1);
            r.z = __uint_as_float(r2);
            r.w = __uint_as_float(r3);
            *(float4*)(ozb + joff) = r;
        }

        group_bar(g);   // all readers of this buffer done before it is re-staged
    }
}

extern "C" void kernel_launch(void* const* d_in, const int* in_sizes, int n_in,
                              void* d_out, int out_size) {
    const float* x0 = (const float*)d_in[0];
    const float* x1 = (const float*)d_in[1];
    const float* x2 = (const float*)d_in[2];
    const float* coeff = (const float*)d_in[3];
    const int*   pidx = (const int*)d_in[4];
    float* out = (float*)d_out;

    const int P = in_sizes[3];            // 64
    const int Z = in_sizes[0] / SU;       // 20000

    static PrepData* c_prep_dev = nullptr;
    static bool attr_set = false;
    const size_t smem_bytes = (size_t)GROUPS * 2 * TILE_BYTES + GROUPS * 2 * 8 + 64;
    if (!attr_set) {
        void* a = nullptr;
        cudaGetSymbolAddress(&a, c_prep);
        c_prep_dev = (PrepData*)a;
        cudaFuncSetAttribute(ftp4_kernel,
                             cudaFuncAttributeMaxDynamicSharedMemorySize,
                             (int)smem_bytes);
        attr_set = true;
    }

    prep_kernel<<<1, 32>>>(pidx, coeff, P, c_prep_dev);

    // PDL launch: main may begin its prologue while prep runs; the
    // grid-dependency sync inside ftp4_kernel orders prep's writes before
    // any constant read.
    cudaLaunchConfig_t cfg = {};
    cfg.gridDim = dim3(GRID_BLOCKS, 1, 1);
    cfg.blockDim = dim3(NTHREADS, 1, 1);
    cfg.dynamicSmemBytes = smem_bytes;
    cfg.stream = 0;
    cudaLaunchAttribute attrs[1];
    attrs[0].id = cudaLaunchAttributeProgrammaticStreamSerialization;
    attrs[0].val.programmaticStreamSerializationAllowed = 1;
    cfg.attrs = attrs;
    cfg.numAttrs = 1;
    cudaLaunchKernelEx(&cfg, ftp4_kernel, x0, x1, x2, out, Z);
}